// round 6
// baseline (speedup 1.0000x reference)
#include <cuda_runtime.h>
#include <math.h>

#define NG    2048
#define NPG   24
#define EPG   288
#define KGB   32
#define EMB   32
#define DH    64
#define NT    256
#define NPAIR (NPG*NPG)          // 576
#define NATOM 10

typedef unsigned long long ull;

// packed fp32x2 helpers (Blackwell f32x2 pipe — PTX-only)
__device__ __forceinline__ ull pk2(float lo, float hi) {
    ull r; asm("mov.b64 %0, {%1, %2};" : "=l"(r) : "f"(lo), "f"(hi)); return r;
}
__device__ __forceinline__ void upk2(ull v, float& lo, float& hi) {
    asm("mov.b64 {%0, %1}, %2;" : "=f"(lo), "=f"(hi) : "l"(v));
}
__device__ __forceinline__ ull ffma2(ull a, ull b, ull c) {
    ull d; asm("fma.rn.f32x2 %0, %1, %2, %3;" : "=l"(d) : "l"(a), "l"(b), "l"(c)); return d;
}

// shared memory layout (4-byte words) — total 13512 words = 54.0 KB
#define OFF_XV    0                        // 576
#define OFF_PE    (OFF_XV   + NPAIR)       // 9216 (288 edges x 32 k)
#define OFF_S     (OFF_PE   + EPG*KGB)     // 768
#define OFF_GNF   (OFF_S    + NPG*KGB)     // 768
#define OFF_WEP   (OFF_GNF  + NPG*EMB)     // 1024 (512 ull, [kk][m])
#define OFF_MUL   (OFF_WEP  + KGB*EMB)     // 100
#define OFF_BIAS  (OFF_MUL  + NATOM*NATOM) // 100
#define OFF_MEAN  (OFF_BIAS + NATOM*NATOM) // 32
#define OFF_ISTD  (OFF_MEAN + KGB)
#define OFF_NORM  (OFF_ISTD + KGB)
#define OFF_BEP   (OFF_NORM + KGB)
#define OFF_BN    (OFF_BEP  + EMB)
#define OFF_BE    (OFF_BN   + DH)
#define OFF_AE    (OFF_BE   + DH)          // 320
#define OFF_POS   (OFF_AE   + NATOM*EMB)   // 72
#define OFF_EPAIR (OFF_POS  + NPG*3)       // 288 ints
#define OFF_Z     (OFF_EPAIR+ EPG)         // 24 ints
#define SMEM_WORDS (OFF_Z + NPG)
#define SMEM_BYTES (SMEM_WORDS * 4)

extern __shared__ float sm[];

__global__ __launch_bounds__(NT, 4)
void gps_graph_kernel(const int* __restrict__ z,
                      const float* __restrict__ pos,
                      const int* __restrict__ edge_index,
                      const float* __restrict__ atom_emb,
                      const float* __restrict__ Wep,
                      const float* __restrict__ bep,
                      const float* __restrict__ means,
                      const float* __restrict__ stds,
                      const float* __restrict__ gmul,
                      const float* __restrict__ gbias,
                      const float* __restrict__ Wn,
                      const float* __restrict__ bn,
                      const float* __restrict__ We,
                      const float* __restrict__ be,
                      float* __restrict__ out_nodes,
                      float* __restrict__ out_edges,
                      int E)
{
    const int g   = blockIdx.x;
    const int tid = threadIdx.x;
    const int zbase = g * NPG;
    const int ebase = g * EPG;

    float* Xv    = sm + OFF_XV;
    float* Pe    = sm + OFF_PE;
    float* Ssum  = sm + OFF_S;
    float* Gnf   = sm + OFF_GNF;
    ull*   sWep2 = (ull*)(sm + OFF_WEP);
    float* sMul  = sm + OFF_MUL;
    float* sBias = sm + OFF_BIAS;
    float* sMean = sm + OFF_MEAN;
    float* sIstd = sm + OFF_ISTD;
    float* sNorm = sm + OFF_NORM;
    float* sBep  = sm + OFF_BEP;
    float* sBn   = sm + OFF_BN;
    float* sBe   = sm + OFF_BE;
    float* sAe   = sm + OFF_AE;
    float* sPos  = sm + OFF_POS;
    int*   sEPair= (int*)(sm + OFF_EPAIR);
    int*   sZ    = (int*)(sm + OFF_Z);

    // ---- cooperative loads ----
    if (tid < NPG) sZ[tid] = z[zbase + tid];
    for (int t = tid; t < NPG*3; t += NT) sPos[t] = pos[zbase*3 + t];
    for (int t = tid; t < (KGB/2)*EMB; t += NT) {
        int kk = t >> 5, m = t & 31;
        sWep2[kk * EMB + m] = pk2(Wep[(2*kk)*EMB + m], Wep[(2*kk+1)*EMB + m]);
    }
    for (int t = tid; t < NATOM*NATOM; t += NT) { sMul[t] = gmul[t]; sBias[t] = gbias[t]; }
    if (tid < KGB) {
        float s = fabsf(stds[tid]) + 1e-5f;
        sMean[tid] = means[tid];
        sIstd[tid] = 1.0f / s;
        sNorm[tid] = 0.3989422804014327f / s;
    }
    if (tid >= KGB && tid < 2*KGB) sBep[tid - KGB] = bep[tid - KGB];
    if (tid >= 64 && tid < 128)  sBn[tid - 64] = bn[tid - 64];
    if (tid >= 128 && tid < 192) sBe[tid - 128] = be[tid - 128];
    for (int t = tid; t < NATOM*EMB; t += NT) sAe[t] = atom_emb[t];
    __syncthreads();

    // ---- Stage A: per-pair affine arg x = mul[et]*dist + bias[et]; edge pair idx ----
    for (int p = tid; p < NPAIR; p += NT) {
        int i = p / NPG;
        int j = p - i * NPG;
        float dx = sPos[i*3+0] - sPos[j*3+0];
        float dy = sPos[i*3+1] - sPos[j*3+1];
        float dz = sPos[i*3+2] - sPos[j*3+2];
        float sq = dx*dx + dy*dy + dz*dz;
        float dist = (sq == 0.0f) ? 0.0f : sqrtf(sq);
        int et = sZ[i] * NATOM + sZ[j];
        Xv[p] = sMul[et] * dist + sBias[et];
    }
    for (int e = tid; e < EPG; e += NT) {
        int src = edge_index[ebase + e];
        int dst = edge_index[E + ebase + e];
        sEPair[e] = (dst - zbase) * NPG + (src - zbase);   // index into Xv
    }
    __syncthreads();

    // ---- Stage B1: node sums S[i][k] = norm_k * sum_j exp(...) (no P storage) ----
    {
        const int k  = tid & 31;                 // constant across t-steps
        const float mk = sMean[k], ik = sIstd[k], nk = sNorm[k];
        for (int t = tid; t < NPG * KGB; t += NT) {
            int i = t >> 5;
            const float* xr = Xv + i * NPG;      // broadcast within warp
            float s = 0.0f;
            #pragma unroll
            for (int j = 0; j < NPG; ++j) {
                float a = (xr[j] - mk) * ik;
                s += __expf(-0.5f * a * a);
            }
            Ssum[t] = nk * s;
        }
        // ---- Stage B2: edge-only gaussian rows Pe[e][k] ----
        for (int t = tid; t < EPG * KGB; t += NT) {
            int e = t >> 5;
            float x = Xv[sEPair[e]];             // broadcast within warp
            float a = (x - mk) * ik;
            Pe[t] = nk * __expf(-0.5f * a * a);
        }
    }
    __syncthreads();

    // ---- Stage D: gnf = atom_emb[z_i] + S @ Wep + bep (packed over k) ----
    for (int t = tid; t < NPG * EMB; t += NT) {
        int i = t >> 5, m = t & 31;
        const ull* s2 = (const ull*)(Ssum + i * KGB);
        ull acc = 0;
        #pragma unroll
        for (int kk = 0; kk < KGB/2; ++kk)
            acc = ffma2(s2[kk], sWep2[kk * EMB + m], acc);
        float lo, hi; upk2(acc, lo, hi);
        Gnf[t] = sAe[sZ[i] * EMB + m] + sBep[m] + lo + hi;
    }
    __syncthreads();

    // ---- Stage E: node_feat = gnf @ W_nodes + b_nodes (1 dim/thread) ----
    {
        const int d = tid & (DH - 1);
        const int isub = tid >> 6;               // 0..3
        ull w[EMB/2];
        #pragma unroll
        for (int mm = 0; mm < EMB/2; ++mm)
            w[mm] = pk2(Wn[(2*mm)*DH + d], Wn[(2*mm+1)*DH + d]);
        const float bd = sBn[d];
        for (int i = isub; i < NPG; i += NT/DH) {
            const ull* g2 = (const ull*)(Gnf + i * EMB);
            ull a0 = 0, a1 = 0;
            #pragma unroll
            for (int mm = 0; mm < EMB/2; mm += 2) {
                a0 = ffma2(g2[mm],   w[mm],   a0);
                a1 = ffma2(g2[mm+1], w[mm+1], a1);
            }
            float l0, h0, l1, h1; upk2(a0, l0, h0); upk2(a1, l1, h1);
            out_nodes[(size_t)(zbase + i) * DH + d] = bd + l0 + h0 + l1 + h1;
        }
    }

    // ---- Stage F: edge_feat = Pe[e] @ W_edges + b_edges ----
    // 2 warps per edge (dim halves); lane = dim; Pe row broadcast, sequential e
    {
        const int warpId = tid >> 5;
        const int lane   = tid & 31;
        const int d      = ((warpId & 1) << 5) | lane;
        ull w[KGB/2];
        #pragma unroll
        for (int kk = 0; kk < KGB/2; ++kk)
            w[kk] = pk2(We[(2*kk)*DH + d], We[(2*kk+1)*DH + d]);
        const float bd = sBe[d];
        for (int e = (warpId >> 1); e < EPG; e += 4) {
            const ulonglong2* pv = (const ulonglong2*)(Pe + e * KGB);
            ull a0 = 0, a1 = 0;
            #pragma unroll
            for (int q = 0; q < 8; ++q) {
                ulonglong2 v = pv[q];
                a0 = ffma2(v.x, w[2*q+0], a0);
                a1 = ffma2(v.y, w[2*q+1], a1);
            }
            float l0, h0, l1, h1; upk2(a0, l0, h0); upk2(a1, l1, h1);
            out_edges[(size_t)(ebase + e) * DH + d] = bd + l0 + h0 + l1 + h1;
        }
    }
}

extern "C" void kernel_launch(void* const* d_in, const int* in_sizes, int n_in,
                              void* d_out, int out_size)
{
    const int*   z    = (const int*)  d_in[0];
    const float* pos  = (const float*)d_in[1];
    const int*   ei   = (const int*)  d_in[3];
    const float* ae   = (const float*)d_in[4];
    const float* Wep  = (const float*)d_in[5];
    const float* bep  = (const float*)d_in[6];
    const float* mea  = (const float*)d_in[7];
    const float* stds = (const float*)d_in[8];
    const float* gmul = (const float*)d_in[9];
    const float* gbia = (const float*)d_in[10];
    const float* Wn   = (const float*)d_in[11];
    const float* bn   = (const float*)d_in[12];
    const float* We   = (const float*)d_in[13];
    const float* be   = (const float*)d_in[14];

    const int N = in_sizes[0];          // 49152
    const int E = in_sizes[3] / 2;      // 589824
    const int g = N / NPG;              // 2048

    float* out_nodes = (float*)d_out;
    float* out_edges = out_nodes + (size_t)N * DH;

    cudaFuncSetAttribute(gps_graph_kernel,
                         cudaFuncAttributeMaxDynamicSharedMemorySize, SMEM_BYTES);

    gps_graph_kernel<<<g, NT, SMEM_BYTES>>>(
        z, pos, ei, ae, Wep, bep, mea, stds, gmul, gbia,
        Wn, bn, We, be, out_nodes, out_edges, E);
}